// round 5
// baseline (speedup 1.0000x reference)
#include <cuda_runtime.h>
#include <math.h>
#include <stdint.h>

// Problem constants
#define Bb   32
#define Tt   12
#define Nn   325
#define Dd   64
#define Hh   4
#define HDd  16
#define Mm   32            // M_SP
#define BT   (Bb*Tt)       // 384
#define ND   (Nn*Dd)       // 20800
#define TND  (Tt*Nn*Dd)    // 249600
#define SCALE 0.25f

// -------------------- scratch (device globals; no allocation) --------------------
__device__ float g_xf[BT*64*64];      // per (b,t): rows 0..31 = cos-DFT of x, rows 32..63 = sin-DFT; cols e (6 MB)
__device__ float g_xc[Bb*TND];        // x @ Wc^T (32 MB)
__device__ float g_anorm[Nn*Nn];      // row-normalized adjacency
__device__ float g_basisC[Mm*Nn];     // cos(2 pi f_m n / N)
__device__ float g_basisS[Mm*Nn];     // sin(2 pi f_m n / N)
__device__ float g_Gt[12*12];         // temporal filter matrix (includes 1/6 * 1/12)
__device__ float g_G[64*64];          // Gram X^T X
__device__ float g_Wc[64*64];         // W_mlp @ W_fc1
__device__ float g_inv[2];            // 1/||q||, 1/||k||

// -------------------- init: anorm rows, DFT basis, Gt, zero G --------------------
__global__ void k_init(const float* __restrict__ adj, const int* __restrict__ sp_modes) {
    int bx = blockIdx.x, tid = threadIdx.x;
    if (bx < Nn) {
        __shared__ float red[128];
        float s = 0.f;
        for (int k = tid; k < Nn; k += 128) s += adj[bx*Nn + k];
        red[tid] = s; __syncthreads();
        for (int o = 64; o > 0; o >>= 1) { if (tid < o) red[tid] += red[tid+o]; __syncthreads(); }
        float inv = 1.0f / red[0];
        for (int k = tid; k < Nn; k += 128) g_anorm[bx*Nn + k] = adj[bx*Nn + k] * inv;
    } else {
        // basis
        for (int i = tid; i < Mm*Nn; i += 128) {
            int m = i / Nn, n = i % Nn;
            int f = sp_modes[m];
            int km = (int)(((long long)f * n) % Nn);
            float a = 2.0f * (float)km / (float)Nn;   // in [0,2)
            g_basisC[i] = cospif(a);
            g_basisS[i] = sinpif(a);
        }
        // temporal filter: Gt[t,t'] = (1/72) [1 + 2 sum_{f=1..5} cos(2 pi f (t-t')/12)]
        for (int i = tid; i < 144; i += 128) {
            int t = i / 12, t2 = i % 12;
            float acc = 1.0f;
            for (int f = 1; f <= 5; f++) acc += 2.0f * cospif((float)(f*(t - t2)) / 6.0f);
            g_Gt[i] = acc * (1.0f/72.0f);
        }
        for (int i = tid; i < 4096; i += 128) g_G[i] = 0.f;
    }
}

// -------------------- Gram: G = X^T X over all B*T*N rows --------------------
__global__ __launch_bounds__(256) void k_gram(const float* __restrict__ x) {
    __shared__ float xs[16][68];
    int tid = threadIdx.x; int ty = tid >> 4, tx = tid & 15;
    float acc[4][4] = {};
    const int nrows = Bb*Tt*Nn;            // 124800
    const int nch = (nrows + 15) / 16;     // 7800
    for (int c = blockIdx.x; c < nch; c += gridDim.x) {
        int r0 = c * 16;
        for (int i = tid; i < 16*64; i += 256) {
            int r = i >> 6, e = i & 63;
            xs[r][e] = (r0 + r < nrows) ? x[(size_t)(r0 + r)*64 + e] : 0.f;
        }
        __syncthreads();
        #pragma unroll
        for (int r = 0; r < 16; r++) {
            float a[4], b[4];
            #pragma unroll
            for (int i = 0; i < 4; i++) a[i] = xs[r][ty*4 + i];
            #pragma unroll
            for (int j = 0; j < 4; j++) b[j] = xs[r][tx*4 + j];
            #pragma unroll
            for (int i = 0; i < 4; i++)
                #pragma unroll
                for (int j = 0; j < 4; j++) acc[i][j] = fmaf(a[i], b[j], acc[i][j]);
        }
        __syncthreads();
    }
    #pragma unroll
    for (int i = 0; i < 4; i++)
        #pragma unroll
        for (int j = 0; j < 4; j++)
            atomicAdd(&g_G[(ty*4 + i)*64 + tx*4 + j], acc[i][j]);
}

// -------------------- norms (via Gram) + combined GCN weight --------------------
__global__ __launch_bounds__(256) void k_norm(const float* __restrict__ Wq, const float* __restrict__ Wk,
                                              const float* __restrict__ Wmlp, const float* __restrict__ Wfc1) {
    __shared__ float Gs[4096];
    __shared__ float red[256];
    int tid = threadIdx.x;
    for (int i = tid; i < 4096; i += 256) Gs[i] = g_G[i];
    __syncthreads();
    float sq = 0.f, sk = 0.f;
    for (int p = tid; p < 4096; p += 256) {
        int d = p >> 6, f = p & 63;
        float aq = 0.f, ak = 0.f;
        #pragma unroll 8
        for (int e = 0; e < 64; e++) {
            float g = Gs[e*64 + f];
            aq = fmaf(Wq[d*64 + e], g, aq);
            ak = fmaf(Wk[d*64 + e], g, ak);
        }
        sq = fmaf(aq, Wq[d*64 + f], sq);
        sk = fmaf(ak, Wk[d*64 + f], sk);
    }
    red[tid] = sq; __syncthreads();
    for (int o = 128; o > 0; o >>= 1) { if (tid < o) red[tid] += red[tid+o]; __syncthreads(); }
    if (tid == 0) g_inv[0] = 1.0f / sqrtf(red[0]);
    __syncthreads();
    red[tid] = sk; __syncthreads();
    for (int o = 128; o > 0; o >>= 1) { if (tid < o) red[tid] += red[tid+o]; __syncthreads(); }
    if (tid == 0) g_inv[1] = 1.0f / sqrtf(red[0]);
    // Wc[e2,d] = sum_e Wmlp[e2,e] * Wfc1[e,d]
    for (int p = tid; p < 4096; p += 256) {
        int e2 = p >> 6, d = p & 63;
        float a = 0.f;
        #pragma unroll 8
        for (int e = 0; e < 64; e++) a = fmaf(Wmlp[e2*64 + e], Wfc1[e*64 + d], a);
        g_Wc[e2*64 + d] = a;
    }
}

// -------------------- batched DFT: xf[bt] = Basis(64x325) @ x_slice(325x64) --------------------
__global__ __launch_bounds__(256) void k_dft(const float* __restrict__ x) {
    int bt = blockIdx.x;
    __shared__ float As[64*25];
    __shared__ float Bs[25*68];
    int tid = threadIdx.x, ty = tid >> 4, tx = tid & 15;
    float acc[4][4] = {};
    const float* xb = x + (size_t)bt * ND;
    for (int k0 = 0; k0 < Nn; k0 += 25) {
        for (int i = tid; i < 64*25; i += 256) {
            int r = i / 25, kk = i % 25;
            As[i] = (r < 32) ? g_basisC[r*Nn + k0 + kk] : g_basisS[(r-32)*Nn + k0 + kk];
        }
        for (int i = tid; i < 25*64; i += 256) {
            int kk = i >> 6, j = i & 63;
            Bs[kk*68 + j] = xb[(k0 + kk)*64 + j];
        }
        __syncthreads();
        #pragma unroll
        for (int kk = 0; kk < 25; kk++) {
            float a[4], b[4];
            #pragma unroll
            for (int i = 0; i < 4; i++) a[i] = As[(ty*4 + i)*25 + kk];
            #pragma unroll
            for (int j = 0; j < 4; j++) b[j] = Bs[kk*68 + tx*4 + j];
            #pragma unroll
            for (int i = 0; i < 4; i++)
                #pragma unroll
                for (int j = 0; j < 4; j++) acc[i][j] = fmaf(a[i], b[j], acc[i][j]);
        }
        __syncthreads();
    }
    float* o = g_xf + (size_t)bt * 4096;
    #pragma unroll
    for (int i = 0; i < 4; i++)
        #pragma unroll
        for (int j = 0; j < 4; j++) o[(ty*4 + i)*64 + tx*4 + j] = acc[i][j];
}

// -------------------- xc = X @ Wc^T --------------------
__global__ __launch_bounds__(256) void k_xc(const float* __restrict__ x) {
    __shared__ float Xs[64*65];
    __shared__ float Ws[64*65];
    int tid = threadIdx.x, ty = tid >> 4, tx = tid & 15;
    int r0 = blockIdx.x * 64;   // 1950 blocks, 124800 rows exact
    for (int i = tid; i < 4096; i += 256) { int d = i >> 6, e = i & 63; Ws[d*65 + e] = g_Wc[i]; }
    for (int i = tid; i < 4096; i += 256) { int r = i >> 6, e = i & 63; Xs[r*65 + e] = x[(size_t)(r0 + r)*64 + e]; }
    __syncthreads();
    float acc[4][4] = {};
    #pragma unroll 8
    for (int e = 0; e < 64; e++) {
        float a[4], b[4];
        #pragma unroll
        for (int i = 0; i < 4; i++) a[i] = Xs[(ty*4 + i)*65 + e];
        #pragma unroll
        for (int j = 0; j < 4; j++) b[j] = Ws[(tx*4 + j)*65 + e];
        #pragma unroll
        for (int i = 0; i < 4; i++)
            #pragma unroll
            for (int j = 0; j < 4; j++) acc[i][j] = fmaf(a[i], b[j], acc[i][j]);
    }
    #pragma unroll
    for (int i = 0; i < 4; i++)
        #pragma unroll
        for (int j = 0; j < 4; j++) g_xc[(size_t)(r0 + ty*4 + i)*64 + tx*4 + j] = acc[i][j];
}

// -------------------- GCN: out[bt] = anorm @ xc[bt] + b_mlp (writes out) --------------------
__global__ __launch_bounds__(256) void k_gcn(const float* __restrict__ bmlp, float* __restrict__ out) {
    int bt = blockIdx.x / 6, rt = blockIdx.x % 6;
    int n0 = rt * 64;
    int rows = Nn - n0; if (rows > 64) rows = 64;
    __shared__ float As[64*26];
    __shared__ float Bs[25*68];
    int tid = threadIdx.x, ty = tid >> 4, tx = tid & 15;
    float acc[4][4] = {};
    const float* xcb = g_xc + (size_t)bt * ND;
    for (int k0 = 0; k0 < Nn; k0 += 25) {
        for (int i = tid; i < 64*25; i += 256) {
            int r = i / 25, kk = i % 25;
            As[r*26 + kk] = (r < rows) ? g_anorm[(n0 + r)*Nn + k0 + kk] : 0.f;
        }
        for (int i = tid; i < 25*64; i += 256) {
            int kk = i >> 6, j = i & 63;
            Bs[kk*68 + j] = xcb[(k0 + kk)*64 + j];
        }
        __syncthreads();
        #pragma unroll
        for (int kk = 0; kk < 25; kk++) {
            float a[4], b[4];
            #pragma unroll
            for (int i = 0; i < 4; i++) a[i] = As[(ty*4 + i)*26 + kk];
            #pragma unroll
            for (int j = 0; j < 4; j++) b[j] = Bs[kk*68 + tx*4 + j];
            #pragma unroll
            for (int i = 0; i < 4; i++)
                #pragma unroll
                for (int j = 0; j < 4; j++) acc[i][j] = fmaf(a[i], b[j], acc[i][j]);
        }
        __syncthreads();
    }
    #pragma unroll
    for (int i = 0; i < 4; i++) {
        int n = n0 + ty*4 + i;
        if (n < Nn) {
            #pragma unroll
            for (int j = 0; j < 4; j++)
                out[(size_t)bt*ND + n*64 + tx*4 + j] = acc[i][j] + bmlp[tx*4 + j];
        }
    }
}

// -------------------- temporal: out += Gt @ (x_rows @ Wv_t^T), per (b,n) --------------------
__global__ __launch_bounds__(128) void k_temporal(const float* __restrict__ x, const float* __restrict__ Wvt,
                                                  float* __restrict__ out) {
    int b = blockIdx.x / Nn, n = blockIdx.x % Nn;
    __shared__ float xs[12*64];
    __shared__ float Wvs[64*65];
    __shared__ float Vs[12*64];
    __shared__ float Gts[144];
    int tid = threadIdx.x;
    const float* xb = x + (size_t)b * TND + n * 768;   // 12 consecutive rows in (T*N) space
    for (int i = tid; i < 768; i += 128) xs[i] = xb[i];
    for (int i = tid; i < 4096; i += 128) { int d = i >> 6, e = i & 63; Wvs[d*65 + e] = Wvt[i]; }
    for (int i = tid; i < 144; i += 128) Gts[i] = g_Gt[i];
    __syncthreads();
    int d = tid & 63, t0 = tid >> 6;
    for (int t = t0; t < 12; t += 2) {
        float a = 0.f;
        #pragma unroll 8
        for (int e = 0; e < 64; e++) a = fmaf(xs[t*64 + e], Wvs[d*65 + e], a);
        Vs[t*64 + d] = a;
    }
    __syncthreads();
    float* ob = out + (size_t)b * TND + n * 64 + d;
    for (int t = t0; t < 12; t += 2) {
        float a = 0.f;
        #pragma unroll
        for (int tp = 0; tp < 12; tp++) a = fmaf(Gts[t*12 + tp], Vs[tp*64 + d], a);
        ob[(size_t)t * ND] += a;
    }
}

// -------------------- spatial attention (fused proj + softmax + irfft), per (b,t,h) --------------------
#define SPATT_SMEM_FLOATS (16384 + 3584)
__global__ __launch_bounds__(256) void k_spatt(const float* __restrict__ Wq, const float* __restrict__ Wk,
                                               const float* __restrict__ Wv, const float* __restrict__ wQ,
                                               const int* __restrict__ sp_modes, float* __restrict__ out) {
    extern __shared__ float sm[];
    float* sW   = sm;                 // 16384 floats: exp weights [m1][m2][hd]
    float* sxC  = sm;                 // overlay (phase A): 2048
    float* sxS  = sm + 2048;          // 2048
    float* sW3  = sm + 4096;          // 3 * 16*65 = 3120 (Wq/Wk/Wv head rows, padded)
    float* pers = sm + 16384;
    float* magq = pers;               // 512
    float* magk = pers + 512;         // 512
    float* vRe  = pers + 1024;        // 512
    float* vIm  = pers + 1536;        // 512
    float* dinv = pers + 2048;        // 512
    float* oRe  = pers + 2560;        // 512 (pre-scaled)
    float* oIs  = pers + 3072;        // 512 (= -Im * scale, added with +sin)

    int tid = threadIdx.x;
    int bt = blockIdx.x >> 2;
    int h  = blockIdx.x & 3;

    // ---- phase A: load xf + head weights, compute magnitudes & vf ----
    const float* xfb = g_xf + (size_t)bt * 4096;
    for (int i = tid; i < 2048; i += 256) { sxC[i] = xfb[i]; sxS[i] = xfb[2048 + i]; }
    for (int i = tid; i < 16*64; i += 256) {
        int hd = i >> 6, e = i & 63;
        int row = h*16 + hd;
        sW3[hd*65 + e]          = Wq[row*64 + e];
        sW3[1040 + hd*65 + e]   = Wk[row*64 + e];
        sW3[2080 + hd*65 + e]   = Wv[row*64 + e];
    }
    __syncthreads();
    float invq = g_inv[0], invk = g_inv[1];
    #pragma unroll
    for (int rep = 0; rep < 2; rep++) {
        int p = tid + rep*256;            // (m, hd)
        int m = p >> 4, hd = p & 15;
        float qC=0.f,qS=0.f,kC=0.f,kS=0.f,vC=0.f,vS=0.f;
        #pragma unroll 4
        for (int e = 0; e < 64; e++) {
            float xc = sxC[m*64 + e], xs = sxS[m*64 + e];
            float wq = sW3[hd*65 + e], wk = sW3[1040 + hd*65 + e], wv = sW3[2080 + hd*65 + e];
            qC = fmaf(xc, wq, qC); qS = fmaf(xs, wq, qS);
            kC = fmaf(xc, wk, kC); kS = fmaf(xs, wk, kS);
            vC = fmaf(xc, wv, vC); vS = fmaf(xs, wv, vS);
        }
        magq[p] = sqrtf(qC*qC + qS*qS) * invq;
        magk[p] = sqrtf(kC*kC + kS*kS) * invk;
        vRe[p]  = vC;          // Re vf = xfC @ Wv
        vIm[p]  = -vS;         // Im vf = -(xfS @ Wv)
    }
    __syncthreads();

    // ---- phase B: exp weights + row denominators (softmax over m2) ----
    #pragma unroll
    for (int rep = 0; rep < 2; rep++) {
        int p = tid + rep*256;            // (m1, hd)
        int m1 = p >> 4, hd = p & 15;
        float mq = magq[m1*16 + hd];
        // m2 = 0 (query-magnitude column)
        float l0 = SCALE * magk[hd] * mq;
        float e0;
        {
            float t = fmaf(l0, 0.0416666667f, 0.1666666667f);
            t = fmaf(l0, t, 0.5f); t = fmaf(l0, t, 1.0f);
            e0 = (l0 < 0.25f) ? fmaf(l0, t, 1.0f) : __expf(l0);
        }
        sW[(m1*32)*16 + hd] = e0;
        float den = e0;
        #pragma unroll 4
        for (int m2 = 1; m2 < 32; m2++) {
            float amp = fabsf(wQ[(m1*31 + m2 - 1)*16 + hd]);
            float l = SCALE * magk[m2*16 + hd] * amp;
            float t = fmaf(l, 0.0416666667f, 0.1666666667f);
            t = fmaf(l, t, 0.5f); t = fmaf(l, t, 1.0f);
            float e = (l < 0.25f) ? fmaf(l, t, 1.0f) : __expf(l);
            sW[(m1*32 + m2)*16 + hd] = e;
            den += e;
        }
        dinv[p] = 1.0f / den;
    }
    __syncthreads();

    // ---- phase C: mean over m1, scale, multiply vf ----
    #pragma unroll
    for (int rep = 0; rep < 2; rep++) {
        int p = tid + rep*256;            // (m2, hd)
        int m2 = p >> 4;
        float s = 0.f;
        #pragma unroll 8
        for (int m1 = 0; m1 < 32; m1++)
            s = fmaf(sW[(m1*32 + m2)*16 + (p & 15)], dinv[m1*16 + (p & 15)], s);
        int f = sp_modes[m2];
        float c = s * (1.0f/32.0f) * ((f == 0) ? 1.0f : 2.0f) * (1.0f/(float)Nn);
        oRe[p] = vRe[p] * c;
        oIs[p] = -vIm[p] * c;             // contribution = oRe*cos + oIs*sin
    }
    __syncthreads();

    // ---- phase D: inverse DFT, accumulate into out ----
    for (int n = tid; n < Nn; n += 256) {
        float acc[16];
        #pragma unroll
        for (int hd = 0; hd < 16; hd++) acc[hd] = 0.f;
        #pragma unroll 4
        for (int m = 0; m < 32; m++) {
            float c = g_basisC[m*Nn + n], s = g_basisS[m*Nn + n];
            #pragma unroll
            for (int hd = 0; hd < 16; hd++)
                acc[hd] = fmaf(oRe[m*16 + hd], c, fmaf(oIs[m*16 + hd], s, acc[hd]));
        }
        float4* o4 = (float4*)(out + (size_t)bt*ND + n*64 + h*16);
        #pragma unroll
        for (int q4 = 0; q4 < 4; q4++) {
            float4 v = o4[q4];
            v.x += acc[q4*4 + 0]; v.y += acc[q4*4 + 1];
            v.z += acc[q4*4 + 2]; v.w += acc[q4*4 + 3];
            o4[q4] = v;
        }
    }
}

// -------------------- launch --------------------
extern "C" void kernel_launch(void* const* d_in, const int* in_sizes, int n_in,
                              void* d_out, int out_size) {
    const float* x      = (const float*)d_in[0];
    const float* adj    = (const float*)d_in[1];
    const float* Wq_geo = (const float*)d_in[2];
    const float* Wk_geo = (const float*)d_in[3];
    const float* Wv_geo = (const float*)d_in[4];
    const float* Wv_t   = (const float*)d_in[7];
    const float* W_fc1  = (const float*)d_in[8];
    const float* W_mlp  = (const float*)d_in[9];
    const float* b_mlp  = (const float*)d_in[10];
    const float* wQ     = (const float*)d_in[11];
    const int*   sp_m   = (const int*)d_in[13];
    float* out = (float*)d_out;

    cudaFuncSetAttribute(k_spatt, cudaFuncAttributeMaxDynamicSharedMemorySize,
                         SPATT_SMEM_FLOATS * (int)sizeof(float));

    k_init    <<<Nn + 1, 128>>>(adj, sp_m);
    k_gram    <<<148, 256>>>(x);
    k_norm    <<<1, 256>>>(Wq_geo, Wk_geo, W_mlp, W_fc1);
    k_dft     <<<BT, 256>>>(x);
    k_xc      <<<(Bb*Tt*Nn)/64, 256>>>(x);
    k_gcn     <<<BT*6, 256>>>(b_mlp, out);              // writes every output element
    k_temporal<<<Bb*Nn, 128>>>(x, Wv_t, out);           // accumulates
    k_spatt   <<<BT*Hh, 256, SPATT_SMEM_FLOATS * sizeof(float)>>>(Wq_geo, Wk_geo, Wv_geo, wQ, sp_m, out);
}

// round 6
// speedup vs baseline: 1.1317x; 1.1317x over previous
#include <cuda_runtime.h>
#include <math.h>
#include <stdint.h>

// Problem constants
#define Bb   32
#define Tt   12
#define Nn   325
#define Dd   64
#define Hh   4
#define HDd  16
#define Mm   32            // M_SP
#define BT   (Bb*Tt)       // 384
#define ND   (Nn*Dd)       // 20800
#define TND  (Tt*Nn*Dd)    // 249600
#define NCOL (BT*64)       // 24576 columns of the transposed xc
#define SCALE 0.25f

// -------------------- scratch (device globals; no allocation) --------------------
__device__ float g_xf[BT*64*64];      // per (b,t): rows 0..31 = cos-DFT, 32..63 = sin-DFT (6 MB)
__device__ float g_xcT[Nn*NCOL];      // (x @ Wc^T) transposed: [k][bt*64+d]  (32 MB)
__device__ float g_vt[BT*Nn*64];      // x @ Wvt^T, row layout (32 MB)
__device__ float g_anorm[Nn*Nn];      // row-normalized adjacency
__device__ float g_anormT[Nn*Nn];     // its transpose
__device__ float g_basisC[Mm*Nn];
__device__ float g_basisS[Mm*Nn];
__device__ float g_Gt[12*12];         // temporal filter (includes 1/6 * 1/12)
__device__ float g_G[64*64];          // Gram X^T X
__device__ float g_Wc[64*64];         // W_mlp @ W_fc1
__device__ float g_inv[2];            // 1/||q||, 1/||k||

// -------------------- init: anorm rows (+T), DFT basis, Gt, zero G --------------------
__global__ void k_init(const float* __restrict__ adj, const int* __restrict__ sp_modes) {
    int bx = blockIdx.x, tid = threadIdx.x;
    if (bx < Nn) {
        __shared__ float red[128];
        float s = 0.f;
        for (int k = tid; k < Nn; k += 128) s += adj[bx*Nn + k];
        red[tid] = s; __syncthreads();
        for (int o = 64; o > 0; o >>= 1) { if (tid < o) red[tid] += red[tid+o]; __syncthreads(); }
        float inv = 1.0f / red[0];
        for (int k = tid; k < Nn; k += 128) {
            float v = adj[bx*Nn + k] * inv;
            g_anorm[bx*Nn + k] = v;
            g_anormT[k*Nn + bx] = v;
        }
    } else {
        for (int i = tid; i < Mm*Nn; i += 128) {
            int m = i / Nn, n = i % Nn;
            int f = sp_modes[m];
            int km = (int)(((long long)f * n) % Nn);
            float a = 2.0f * (float)km / (float)Nn;
            g_basisC[i] = cospif(a);
            g_basisS[i] = sinpif(a);
        }
        for (int i = tid; i < 144; i += 128) {
            int t = i / 12, t2 = i % 12;
            float acc = 1.0f;
            for (int f = 1; f <= 5; f++) acc += 2.0f * cospif((float)(f*(t - t2)) / 6.0f);
            g_Gt[i] = acc * (1.0f/72.0f);
        }
        for (int i = tid; i < 4096; i += 128) g_G[i] = 0.f;
    }
}

// -------------------- Gram: G = X^T X --------------------
__global__ __launch_bounds__(256) void k_gram(const float* __restrict__ x) {
    __shared__ float xs[16][68];
    int tid = threadIdx.x; int ty = tid >> 4, tx = tid & 15;
    float acc[4][4] = {};
    const int nrows = Bb*Tt*Nn;
    const int nch = (nrows + 15) / 16;
    for (int c = blockIdx.x; c < nch; c += gridDim.x) {
        int r0 = c * 16;
        for (int i = tid; i < 16*64; i += 256) {
            int r = i >> 6, e = i & 63;
            xs[r][e] = (r0 + r < nrows) ? x[(size_t)(r0 + r)*64 + e] : 0.f;
        }
        __syncthreads();
        #pragma unroll
        for (int r = 0; r < 16; r++) {
            float a[4], b[4];
            #pragma unroll
            for (int i = 0; i < 4; i++) a[i] = xs[r][ty*4 + i];
            #pragma unroll
            for (int j = 0; j < 4; j++) b[j] = xs[r][tx*4 + j];
            #pragma unroll
            for (int i = 0; i < 4; i++)
                #pragma unroll
                for (int j = 0; j < 4; j++) acc[i][j] = fmaf(a[i], b[j], acc[i][j]);
        }
        __syncthreads();
    }
    #pragma unroll
    for (int i = 0; i < 4; i++)
        #pragma unroll
        for (int j = 0; j < 4; j++)
            atomicAdd(&g_G[(ty*4 + i)*64 + tx*4 + j], acc[i][j]);
}

// -------------------- norms via Gram + combined GCN weight --------------------
__global__ __launch_bounds__(256) void k_norm(const float* __restrict__ Wq, const float* __restrict__ Wk,
                                              const float* __restrict__ Wmlp, const float* __restrict__ Wfc1) {
    __shared__ float Gs[4096];
    __shared__ float red[256];
    int tid = threadIdx.x;
    for (int i = tid; i < 4096; i += 256) Gs[i] = g_G[i];
    __syncthreads();
    float sq = 0.f, sk = 0.f;
    for (int p = tid; p < 4096; p += 256) {
        int d = p >> 6, f = p & 63;
        float aq = 0.f, ak = 0.f;
        #pragma unroll 8
        for (int e = 0; e < 64; e++) {
            float g = Gs[e*64 + f];
            aq = fmaf(Wq[d*64 + e], g, aq);
            ak = fmaf(Wk[d*64 + e], g, ak);
        }
        sq = fmaf(aq, Wq[d*64 + f], sq);
        sk = fmaf(ak, Wk[d*64 + f], sk);
    }
    red[tid] = sq; __syncthreads();
    for (int o = 128; o > 0; o >>= 1) { if (tid < o) red[tid] += red[tid+o]; __syncthreads(); }
    if (tid == 0) g_inv[0] = 1.0f / sqrtf(red[0]);
    __syncthreads();
    red[tid] = sk; __syncthreads();
    for (int o = 128; o > 0; o >>= 1) { if (tid < o) red[tid] += red[tid+o]; __syncthreads(); }
    if (tid == 0) g_inv[1] = 1.0f / sqrtf(red[0]);
    for (int p = tid; p < 4096; p += 256) {
        int e2 = p >> 6, d = p & 63;
        float a = 0.f;
        #pragma unroll 8
        for (int e = 0; e < 64; e++) a = fmaf(Wmlp[e2*64 + e], Wfc1[e*64 + d], a);
        g_Wc[e2*64 + d] = a;
    }
}

// -------------------- batched DFT: xf[bt] = Basis(64x325) @ x_slice(325x64) --------------------
__global__ __launch_bounds__(256) void k_dft(const float* __restrict__ x) {
    int bt = blockIdx.x;
    __shared__ float As[64*25];
    __shared__ float Bs[25*68];
    int tid = threadIdx.x, ty = tid >> 4, tx = tid & 15;
    float acc[4][4] = {};
    const float* xb = x + (size_t)bt * ND;
    for (int k0 = 0; k0 < Nn; k0 += 25) {
        for (int i = tid; i < 64*25; i += 256) {
            int r = i / 25, kk = i % 25;
            As[i] = (r < 32) ? g_basisC[r*Nn + k0 + kk] : g_basisS[(r-32)*Nn + k0 + kk];
        }
        for (int i = tid; i < 25*64; i += 256) {
            int kk = i >> 6, j = i & 63;
            Bs[kk*68 + j] = xb[(k0 + kk)*64 + j];
        }
        __syncthreads();
        #pragma unroll
        for (int kk = 0; kk < 25; kk++) {
            float a[4], b[4];
            #pragma unroll
            for (int i = 0; i < 4; i++) a[i] = As[(ty*4 + i)*25 + kk];
            #pragma unroll
            for (int j = 0; j < 4; j++) b[j] = Bs[kk*68 + tx*4 + j];
            #pragma unroll
            for (int i = 0; i < 4; i++)
                #pragma unroll
                for (int j = 0; j < 4; j++) acc[i][j] = fmaf(a[i], b[j], acc[i][j]);
        }
        __syncthreads();
    }
    float* o = g_xf + (size_t)bt * 4096;
    #pragma unroll
    for (int i = 0; i < 4; i++)
        #pragma unroll
        for (int j = 0; j < 4; j++) o[(ty*4 + i)*64 + tx*4 + j] = acc[i][j];
}

// -------------------- fused projection: [xcT | vt] = x @ [Wc ; Wvt]^T --------------------
// dynamic smem: Xs[64*65] + Ws[64*132]  (Ws stored transposed: Ws[e*132 + c])
#define PROJT_SMEM ((64*65 + 64*132) * 4)
__global__ __launch_bounds__(256) void k_projT(const float* __restrict__ x, const float* __restrict__ Wvt) {
    extern __shared__ float sm[];
    float* Xs = sm;            // [row][e], stride 65
    float* Ws = sm + 64*65;    // [e][c],  stride 132, c<64 -> Wc row c, c>=64 -> Wvt row c-64
    int tid = threadIdx.x, ty = tid >> 4, tx = tid & 15;
    int r0 = blockIdx.x * 64;          // 1950 blocks, exact
    for (int i = tid; i < 64*64; i += 256) {
        int r = i >> 6, e = i & 63;
        Xs[r*65 + e] = x[(size_t)(r0 + r)*64 + e];
    }
    for (int i = tid; i < 128*64; i += 256) {
        int c = i >> 6, e = i & 63;   // coalesced gmem read over e
        float w = (c < 64) ? g_Wc[c*64 + e] : Wvt[(c-64)*64 + e];
        Ws[e*132 + c] = w;
    }
    __syncthreads();
    float acc[4][8] = {};
    #pragma unroll 8
    for (int e = 0; e < 64; e++) {
        float a[4], b[8];
        #pragma unroll
        for (int i = 0; i < 4; i++) a[i] = Xs[(ty*4 + i)*65 + e];
        #pragma unroll
        for (int j = 0; j < 8; j++) b[j] = Ws[e*132 + tx*8 + j];
        #pragma unroll
        for (int i = 0; i < 4; i++)
            #pragma unroll
            for (int j = 0; j < 8; j++) acc[i][j] = fmaf(a[i], b[j], acc[i][j]);
    }
    #pragma unroll
    for (int i = 0; i < 4; i++) {
        int r = r0 + ty*4 + i;
        int bt = r / Nn, n = r - bt*Nn;
        if (tx < 8) {   // xc -> transposed layout [n][bt*64+d]
            float* o = g_xcT + (size_t)n*NCOL + bt*64 + tx*8;
            #pragma unroll
            for (int j = 0; j < 8; j++) o[j] = acc[i][j];
        } else {        // vt -> row layout
            float* o = g_vt + (size_t)r*64 + (tx*8 - 64);
            #pragma unroll
            for (int j = 0; j < 8; j++) o[j] = acc[i][j];
        }
    }
}

// -------------------- GCN as ONE GEMM: out = anorm(325x325) @ xcT(325x24576) + bias --------------------
__global__ __launch_bounds__(256) void k_gcn2(const float* __restrict__ bmlp, float* __restrict__ out) {
    __shared__ float As[16][132];   // As[kk][i] = anormT[(k0+kk)*325 + n0+i]
    __shared__ float Bs[16][132];   // Bs[kk][j] = xcT[(k0+kk)*NCOL + c0+j]
    __shared__ float bsm[128];
    int tid = threadIdx.x, ty = tid >> 4, tx = tid & 15;
    int c0 = blockIdx.x * 128;
    int n0 = blockIdx.y * 128;
    if (tid < 128) bsm[tid] = bmlp[(c0 + tid) & 63];
    float acc[8][8] = {};
    for (int k0 = 0; k0 < Nn; k0 += 16) {
        for (int i = tid; i < 2048; i += 256) {
            int kk = i >> 7, col = i & 127;
            int k = k0 + kk;
            As[kk][col] = (k < Nn && n0 + col < Nn) ? g_anormT[k*Nn + n0 + col] : 0.f;
            Bs[kk][col] = (k < Nn) ? g_xcT[(size_t)k*NCOL + c0 + col] : 0.f;
        }
        __syncthreads();
        #pragma unroll
        for (int kk = 0; kk < 16; kk++) {
            float a[8], b[8];
            #pragma unroll
            for (int i = 0; i < 8; i++) a[i] = As[kk][ty*8 + i];
            #pragma unroll
            for (int j = 0; j < 8; j++) b[j] = Bs[kk][tx*8 + j];
            #pragma unroll
            for (int i = 0; i < 8; i++)
                #pragma unroll
                for (int j = 0; j < 8; j++) acc[i][j] = fmaf(a[i], b[j], acc[i][j]);
        }
        __syncthreads();
    }
    // epilogue: c = c0 + tx*8 + j encodes (bt = c>>6, d = c&63); 8-col group stays in one bt
    int cloc = tx*8;
    int bt = (c0 + cloc) >> 6;
    int d  = (c0 + cloc) & 63;
    #pragma unroll
    for (int i = 0; i < 8; i++) {
        int n = n0 + ty*8 + i;
        if (n < Nn) {
            float* o = out + (size_t)bt*ND + n*64 + d;
            #pragma unroll
            for (int j = 0; j < 8; j++) o[j] = acc[i][j] + bsm[cloc + j];
        }
    }
}

// -------------------- temporal: out += Gt-filter over 12-row groups of vt --------------------
__global__ __launch_bounds__(256) void k_tfilt(float* __restrict__ out) {
    __shared__ float Gts[144];
    int tid = threadIdx.x;
    if (tid < 144) Gts[tid] = g_Gt[tid];
    __syncthreads();
    int b = blockIdx.y;
    int base = blockIdx.x * 256 + tid;       // index into (g,d) space, < 20800
    if (base >= ND) return;
    int g = base >> 6, d = base & 63;
    const float* vb = g_vt + ((size_t)b*3900 + g*12)*64 + d;
    float v[12];
    #pragma unroll
    for (int tp = 0; tp < 12; tp++) v[tp] = vb[tp*64];
    float* ob = out + (size_t)b*TND + base;
    #pragma unroll
    for (int t = 0; t < 12; t++) {
        float a = 0.f;
        #pragma unroll
        for (int tp = 0; tp < 12; tp++) a = fmaf(Gts[t*12 + tp], v[tp], a);
        ob[(size_t)t*ND] += a;
    }
}

// -------------------- spatial attention (fused proj + softmax + irfft), per (b,t,h) --------------------
#define SPATT_SMEM_FLOATS (16384 + 3584)
__global__ __launch_bounds__(256) void k_spatt(const float* __restrict__ Wq, const float* __restrict__ Wk,
                                               const float* __restrict__ Wv, const float* __restrict__ wQ,
                                               const int* __restrict__ sp_modes, float* __restrict__ out) {
    extern __shared__ float sm[];
    float* sW   = sm;                 // 16384: exp weights [m1][m2][hd]
    float* sxC  = sm;                 // overlay (phase A)
    float* sxS  = sm + 2048;
    float* sW3  = sm + 4096;
    float* pers = sm + 16384;
    float* magq = pers;
    float* magk = pers + 512;
    float* vRe  = pers + 1024;
    float* vIm  = pers + 1536;
    float* dinv = pers + 2048;
    float* oRe  = pers + 2560;
    float* oIs  = pers + 3072;

    int tid = threadIdx.x;
    int bt = blockIdx.x >> 2;
    int h  = blockIdx.x & 3;

    const float* xfb = g_xf + (size_t)bt * 4096;
    for (int i = tid; i < 2048; i += 256) { sxC[i] = xfb[i]; sxS[i] = xfb[2048 + i]; }
    for (int i = tid; i < 16*64; i += 256) {
        int hd = i >> 6, e = i & 63;
        int row = h*16 + hd;
        sW3[hd*65 + e]          = Wq[row*64 + e];
        sW3[1040 + hd*65 + e]   = Wk[row*64 + e];
        sW3[2080 + hd*65 + e]   = Wv[row*64 + e];
    }
    __syncthreads();
    float invq = g_inv[0], invk = g_inv[1];
    #pragma unroll
    for (int rep = 0; rep < 2; rep++) {
        int p = tid + rep*256;
        int m = p >> 4, hd = p & 15;
        float qC=0.f,qS=0.f,kC=0.f,kS=0.f,vC=0.f,vS=0.f;
        #pragma unroll 4
        for (int e = 0; e < 64; e++) {
            float xc = sxC[m*64 + e], xs = sxS[m*64 + e];
            float wq = sW3[hd*65 + e], wk = sW3[1040 + hd*65 + e], wv = sW3[2080 + hd*65 + e];
            qC = fmaf(xc, wq, qC); qS = fmaf(xs, wq, qS);
            kC = fmaf(xc, wk, kC); kS = fmaf(xs, wk, kS);
            vC = fmaf(xc, wv, vC); vS = fmaf(xs, wv, vS);
        }
        magq[p] = sqrtf(qC*qC + qS*qS) * invq;
        magk[p] = sqrtf(kC*kC + kS*kS) * invk;
        vRe[p]  = vC;
        vIm[p]  = -vS;
    }
    __syncthreads();

    #pragma unroll
    for (int rep = 0; rep < 2; rep++) {
        int p = tid + rep*256;
        int m1 = p >> 4, hd = p & 15;
        float mq = magq[m1*16 + hd];
        float l0 = SCALE * magk[hd] * mq;
        float e0;
        {
            float t = fmaf(l0, 0.0416666667f, 0.1666666667f);
            t = fmaf(l0, t, 0.5f); t = fmaf(l0, t, 1.0f);
            e0 = (l0 < 0.25f) ? fmaf(l0, t, 1.0f) : __expf(l0);
        }
        sW[(m1*32)*16 + hd] = e0;
        float den = e0;
        #pragma unroll 4
        for (int m2 = 1; m2 < 32; m2++) {
            float amp = fabsf(wQ[(m1*31 + m2 - 1)*16 + hd]);
            float l = SCALE * magk[m2*16 + hd] * amp;
            float t = fmaf(l, 0.0416666667f, 0.1666666667f);
            t = fmaf(l, t, 0.5f); t = fmaf(l, t, 1.0f);
            float e = (l < 0.25f) ? fmaf(l, t, 1.0f) : __expf(l);
            sW[(m1*32 + m2)*16 + hd] = e;
            den += e;
        }
        dinv[p] = 1.0f / den;
    }
    __syncthreads();

    #pragma unroll
    for (int rep = 0; rep < 2; rep++) {
        int p = tid + rep*256;
        int m2 = p >> 4;
        float s = 0.f;
        #pragma unroll 8
        for (int m1 = 0; m1 < 32; m1++)
            s = fmaf(sW[(m1*32 + m2)*16 + (p & 15)], dinv[m1*16 + (p & 15)], s);
        int f = sp_modes[m2];
        float c = s * (1.0f/32.0f) * ((f == 0) ? 1.0f : 2.0f) * (1.0f/(float)Nn);
        oRe[p] = vRe[p] * c;
        oIs[p] = -vIm[p] * c;
    }
    __syncthreads();

    for (int n = tid; n < Nn; n += 256) {
        float acc[16];
        #pragma unroll
        for (int hd = 0; hd < 16; hd++) acc[hd] = 0.f;
        #pragma unroll 4
        for (int m = 0; m < 32; m++) {
            float c = g_basisC[m*Nn + n], s = g_basisS[m*Nn + n];
            #pragma unroll
            for (int hd = 0; hd < 16; hd++)
                acc[hd] = fmaf(oRe[m*16 + hd], c, fmaf(oIs[m*16 + hd], s, acc[hd]));
        }
        float4* o4 = (float4*)(out + (size_t)bt*ND + n*64 + h*16);
        #pragma unroll
        for (int q4 = 0; q4 < 4; q4++) {
            float4 v = o4[q4];
            v.x += acc[q4*4 + 0]; v.y += acc[q4*4 + 1];
            v.z += acc[q4*4 + 2]; v.w += acc[q4*4 + 3];
            o4[q4] = v;
        }
    }
}

// -------------------- launch --------------------
extern "C" void kernel_launch(void* const* d_in, const int* in_sizes, int n_in,
                              void* d_out, int out_size) {
    const float* x      = (const float*)d_in[0];
    const float* adj    = (const float*)d_in[1];
    const float* Wq_geo = (const float*)d_in[2];
    const float* Wk_geo = (const float*)d_in[3];
    const float* Wv_geo = (const float*)d_in[4];
    const float* Wv_t   = (const float*)d_in[7];
    const float* W_fc1  = (const float*)d_in[8];
    const float* W_mlp  = (const float*)d_in[9];
    const float* b_mlp  = (const float*)d_in[10];
    const float* wQ     = (const float*)d_in[11];
    const int*   sp_m   = (const int*)d_in[13];
    float* out = (float*)d_out;

    cudaFuncSetAttribute(k_spatt, cudaFuncAttributeMaxDynamicSharedMemorySize,
                         SPATT_SMEM_FLOATS * (int)sizeof(float));
    cudaFuncSetAttribute(k_projT, cudaFuncAttributeMaxDynamicSharedMemorySize, PROJT_SMEM);

    k_init  <<<Nn + 1, 128>>>(adj, sp_m);
    k_gram  <<<148, 256>>>(x);
    k_norm  <<<1, 256>>>(Wq_geo, Wk_geo, W_mlp, W_fc1);
    k_dft   <<<BT, 256>>>(x);
    k_projT <<<(Bb*Tt*Nn)/64, 256, PROJT_SMEM>>>(x, Wv_t);
    {
        dim3 g(NCOL/128, 3);
        k_gcn2 <<<g, 256>>>(b_mlp, out);                 // writes every output element
    }
    {
        dim3 g((ND + 255)/256, Bb);
        k_tfilt<<<g, 256>>>(out);                        // accumulates
    }
    k_spatt <<<BT*Hh, 256, SPATT_SMEM_FLOATS * sizeof(float)>>>(Wq_geo, Wk_geo, Wv_geo, wQ, sp_m, out);
}

// round 7
// speedup vs baseline: 1.2113x; 1.0703x over previous
#include <cuda_runtime.h>
#include <math.h>
#include <stdint.h>

// Problem constants
#define Bb   32
#define Tt   12
#define Nn   325
#define Dd   64
#define Hh   4
#define HDd  16
#define Mm   32            // M_SP
#define BT   (Bb*Tt)       // 384
#define ND   (Nn*Dd)       // 20800
#define TND  (Tt*Nn*Dd)    // 249600
#define NCOL (BT*64)       // 24576 columns (bt*64+e / bt*64+d)
#define SCALE 0.25f

// -------------------- scratch (device globals; no allocation) --------------------
__device__ float g_xf[BT*64*64];      // DFT, TRANSPOSED: [m][bt*64+e], m<32 cos, m>=32 sin (6 MB)
__device__ float g_xcT[Nn*NCOL];      // (x @ Wc^T) transposed: [n][bt*64+d]  (32 MB)
__device__ float g_vt[BT*Nn*64];      // x @ Wvt^T, row layout (32 MB)
__device__ float g_anormT[Nn*Nn];     // transpose of row-normalized adjacency
__device__ float g_basisC[Mm*Nn];     // [m][n] cos
__device__ float g_basisS[Mm*Nn];     // [m][n] sin
__device__ float g_basisT[Nn*64];     // [n][m] : m<32 cos, m>=32 sin
__device__ float g_Gt[12*12];         // temporal filter (includes 1/6 * 1/12)
__device__ float g_G[64*64];          // Gram X^T X
__device__ float g_WT[64*128];        // [e][c]: c<64 -> Wc[c][e], c>=64 -> Wvt[c-64][e]
__device__ float g_inv[2];            // 1/||q||, 1/||k||

// -------------------- init: anormT, DFT bases, Gt, zero G --------------------
__global__ void k_init(const float* __restrict__ adj, const int* __restrict__ sp_modes) {
    int bx = blockIdx.x, tid = threadIdx.x;
    if (bx < Nn) {
        __shared__ float red[128];
        float s = 0.f;
        for (int k = tid; k < Nn; k += 128) s += adj[bx*Nn + k];
        red[tid] = s; __syncthreads();
        for (int o = 64; o > 0; o >>= 1) { if (tid < o) red[tid] += red[tid+o]; __syncthreads(); }
        float inv = 1.0f / red[0];
        for (int k = tid; k < Nn; k += 128) {
            g_anormT[k*Nn + bx] = adj[bx*Nn + k] * inv;
        }
    } else {
        for (int i = tid; i < Mm*Nn; i += 128) {
            int m = i / Nn, n = i % Nn;
            int f = sp_modes[m];
            int km = (int)(((long long)f * n) % Nn);
            float a = 2.0f * (float)km / (float)Nn;
            g_basisC[i] = cospif(a);
            g_basisS[i] = sinpif(a);
        }
        for (int i = tid; i < Nn*64; i += 128) {
            int n = i >> 6, m = i & 63;
            int f = sp_modes[m & 31];
            int km = (int)(((long long)f * n) % Nn);
            float a = 2.0f * (float)km / (float)Nn;
            g_basisT[i] = (m < 32) ? cospif(a) : sinpif(a);
        }
        for (int i = tid; i < 144; i += 128) {
            int t = i / 12, t2 = i % 12;
            float acc = 1.0f;
            for (int f = 1; f <= 5; f++) acc += 2.0f * cospif((float)(f*(t - t2)) / 6.0f);
            g_Gt[i] = acc * (1.0f/72.0f);
        }
        for (int i = tid; i < 4096; i += 128) g_G[i] = 0.f;
    }
}

// -------------------- Gram: G = X^T X --------------------
__global__ __launch_bounds__(256) void k_gram(const float* __restrict__ x) {
    __shared__ float xs[16][68];
    int tid = threadIdx.x; int ty = tid >> 4, tx = tid & 15;
    float acc[4][4] = {};
    const int nrows = Bb*Tt*Nn;
    const int nch = (nrows + 15) / 16;
    for (int c = blockIdx.x; c < nch; c += gridDim.x) {
        int r0 = c * 16;
        for (int i = tid; i < 16*64; i += 256) {
            int r = i >> 6, e = i & 63;
            xs[r][e] = (r0 + r < nrows) ? x[(size_t)(r0 + r)*64 + e] : 0.f;
        }
        __syncthreads();
        #pragma unroll
        for (int r = 0; r < 16; r++) {
            float a[4], b[4];
            #pragma unroll
            for (int i = 0; i < 4; i++) a[i] = xs[r][ty*4 + i];
            #pragma unroll
            for (int j = 0; j < 4; j++) b[j] = xs[r][tx*4 + j];
            #pragma unroll
            for (int i = 0; i < 4; i++)
                #pragma unroll
                for (int j = 0; j < 4; j++) acc[i][j] = fmaf(a[i], b[j], acc[i][j]);
        }
        __syncthreads();
    }
    #pragma unroll
    for (int i = 0; i < 4; i++)
        #pragma unroll
        for (int j = 0; j < 4; j++)
            atomicAdd(&g_G[(ty*4 + i)*64 + tx*4 + j], acc[i][j]);
}

// -------------------- norms via Gram + combined projection weight g_WT --------------------
__global__ __launch_bounds__(256) void k_norm(const float* __restrict__ Wq, const float* __restrict__ Wk,
                                              const float* __restrict__ Wmlp, const float* __restrict__ Wfc1,
                                              const float* __restrict__ Wvt) {
    __shared__ float Gs[4096];
    __shared__ float red[256];
    int tid = threadIdx.x;
    for (int i = tid; i < 4096; i += 256) Gs[i] = g_G[i];
    __syncthreads();
    float sq = 0.f, sk = 0.f;
    for (int p = tid; p < 4096; p += 256) {
        int d = p >> 6, f = p & 63;
        float aq = 0.f, ak = 0.f;
        #pragma unroll 8
        for (int e = 0; e < 64; e++) {
            float g = Gs[e*64 + f];
            aq = fmaf(Wq[d*64 + e], g, aq);
            ak = fmaf(Wk[d*64 + e], g, ak);
        }
        sq = fmaf(aq, Wq[d*64 + f], sq);
        sk = fmaf(ak, Wk[d*64 + f], sk);
    }
    red[tid] = sq; __syncthreads();
    for (int o = 128; o > 0; o >>= 1) { if (tid < o) red[tid] += red[tid+o]; __syncthreads(); }
    if (tid == 0) g_inv[0] = 1.0f / sqrtf(red[0]);
    __syncthreads();
    red[tid] = sk; __syncthreads();
    for (int o = 128; o > 0; o >>= 1) { if (tid < o) red[tid] += red[tid+o]; __syncthreads(); }
    if (tid == 0) g_inv[1] = 1.0f / sqrtf(red[0]);
    // Wc[e2][d] = sum_e Wmlp[e2,e]*Wfc1[e,d]; store transposed into g_WT[d*128 + e2]
    for (int p = tid; p < 4096; p += 256) {
        int e2 = p >> 6, d = p & 63;
        float a = 0.f;
        #pragma unroll 8
        for (int e = 0; e < 64; e++) a = fmaf(Wmlp[e2*64 + e], Wfc1[e*64 + d], a);
        g_WT[d*128 + e2] = a;
    }
    // Wvt rows into g_WT[e*128 + 64 + c]
    for (int p = tid; p < 4096; p += 256) {
        int c = p >> 6, e = p & 63;
        g_WT[e*128 + 64 + c] = Wvt[c*64 + e];
    }
}

// -------------------- DFT as one GEMM: g_xf(64 x 24576) = BasisT^T @ Xperm --------------------
__global__ __launch_bounds__(256) void k_dft2(const float* __restrict__ x) {
    __shared__ float As[25*68];    // [kk][m] (68 pad)
    __shared__ float Bs[25*132];   // [kk][col] (132 pad)
    int tid = threadIdx.x, ty = tid >> 4, tx = tid & 15;
    int c0 = blockIdx.x * 128;     // 192 blocks
    float acc[4][8] = {};
    for (int k0 = 0; k0 < Nn; k0 += 25) {
        for (int i = tid; i < 25*64; i += 256) {
            int kk = i >> 6, m = i & 63;
            As[kk*68 + m] = g_basisT[(k0 + kk)*64 + m];
        }
        for (int i = tid; i < 25*128; i += 256) {
            int kk = i / 128, col = i & 127;
            int c = c0 + col;
            int bt = c >> 6, e = c & 63;
            Bs[kk*132 + col] = x[(size_t)bt*ND + (k0 + kk)*64 + e];
        }
        __syncthreads();
        #pragma unroll
        for (int kk = 0; kk < 25; kk++) {
            float a[4], b[8];
            #pragma unroll
            for (int i = 0; i < 4; i++) a[i] = As[kk*68 + ty*4 + i];
            #pragma unroll
            for (int j = 0; j < 8; j++) b[j] = Bs[kk*132 + tx*8 + j];
            #pragma unroll
            for (int i = 0; i < 4; i++)
                #pragma unroll
                for (int j = 0; j < 8; j++) acc[i][j] = fmaf(a[i], b[j], acc[i][j]);
        }
        __syncthreads();
    }
    #pragma unroll
    for (int i = 0; i < 4; i++) {
        float* o = g_xf + (size_t)(ty*4 + i)*NCOL + c0 + tx*8;
        #pragma unroll
        for (int j = 0; j < 8; j++) o[j] = acc[i][j];
    }
}

// -------------------- fused projection: [xcT | vt] = X @ [Wc ; Wvt]^T, 128x128 tiles --------------------
#define PROJT_SMEM ((64*133 + 64*132) * 4)
__global__ __launch_bounds__(256) void k_projT(const float* __restrict__ x) {
    extern __shared__ float sm[];
    float* XsT = sm;            // [e][r], stride 133
    float* Ws  = sm + 64*133;   // [e][c], stride 132
    int tid = threadIdx.x, ty = tid >> 4, tx = tid & 15;
    int r0 = blockIdx.x * 128;  // 975 blocks, exact
    // load X tile transposed (float4 + 4 scalar STS)
    const float4* x4 = (const float4*)(x + (size_t)r0*64);
    for (int i = tid; i < 128*16; i += 256) {
        int r = i >> 4, e4 = i & 15;
        float4 v = x4[r*16 + e4];
        XsT[(e4*4 + 0)*133 + r] = v.x;
        XsT[(e4*4 + 1)*133 + r] = v.y;
        XsT[(e4*4 + 2)*133 + r] = v.z;
        XsT[(e4*4 + 3)*133 + r] = v.w;
    }
    for (int i = tid; i < 64*128; i += 256) {
        int e = i >> 7, c = i & 127;
        Ws[e*132 + c] = g_WT[i];
    }
    __syncthreads();
    float acc[8][8] = {};
    #pragma unroll 4
    for (int e = 0; e < 64; e++) {
        float a[8], b[8];
        #pragma unroll
        for (int i = 0; i < 8; i++) a[i] = XsT[e*133 + ty*8 + i];
        #pragma unroll
        for (int j = 0; j < 8; j++) b[j] = Ws[e*132 + tx*8 + j];
        #pragma unroll
        for (int i = 0; i < 8; i++)
            #pragma unroll
            for (int j = 0; j < 8; j++) acc[i][j] = fmaf(a[i], b[j], acc[i][j]);
    }
    #pragma unroll
    for (int i = 0; i < 8; i++) {
        int r = r0 + ty*8 + i;
        int bt = r / Nn, n = r - bt*Nn;
        if (tx < 8) {   // xc -> transposed layout [n][bt*64+d]
            float* o = g_xcT + (size_t)n*NCOL + bt*64 + tx*8;
            #pragma unroll
            for (int j = 0; j < 8; j++) o[j] = acc[i][j];
        } else {        // vt -> row layout
            float* o = g_vt + (size_t)r*64 + (tx*8 - 64);
            #pragma unroll
            for (int j = 0; j < 8; j++) o[j] = acc[i][j];
        }
    }
}

// -------------------- GCN as ONE GEMM: out = anorm(325x325) @ xcT(325x24576) + bias --------------------
__global__ __launch_bounds__(256) void k_gcn2(const float* __restrict__ bmlp, float* __restrict__ out) {
    __shared__ float As[16][132];
    __shared__ float Bs[16][132];
    __shared__ float bsm[128];
    int tid = threadIdx.x, ty = tid >> 4, tx = tid & 15;
    int c0 = blockIdx.x * 128;
    int n0 = blockIdx.y * 128;
    if (tid < 128) bsm[tid] = bmlp[(c0 + tid) & 63];
    float acc[8][8] = {};
    for (int k0 = 0; k0 < Nn; k0 += 16) {
        for (int i = tid; i < 2048; i += 256) {
            int kk = i >> 7, col = i & 127;
            int k = k0 + kk;
            As[kk][col] = (k < Nn && n0 + col < Nn) ? g_anormT[k*Nn + n0 + col] : 0.f;
            Bs[kk][col] = (k < Nn) ? g_xcT[(size_t)k*NCOL + c0 + col] : 0.f;
        }
        __syncthreads();
        #pragma unroll
        for (int kk = 0; kk < 16; kk++) {
            float a[8], b[8];
            #pragma unroll
            for (int i = 0; i < 8; i++) a[i] = As[kk][ty*8 + i];
            #pragma unroll
            for (int j = 0; j < 8; j++) b[j] = Bs[kk][tx*8 + j];
            #pragma unroll
            for (int i = 0; i < 8; i++)
                #pragma unroll
                for (int j = 0; j < 8; j++) acc[i][j] = fmaf(a[i], b[j], acc[i][j]);
        }
        __syncthreads();
    }
    int cloc = tx*8;
    int bt = (c0 + cloc) >> 6;
    int d  = (c0 + cloc) & 63;
    #pragma unroll
    for (int i = 0; i < 8; i++) {
        int n = n0 + ty*8 + i;
        if (n < Nn) {
            float* o = out + (size_t)bt*ND + n*64 + d;
            #pragma unroll
            for (int j = 0; j < 8; j++) o[j] = acc[i][j] + bsm[cloc + j];
        }
    }
}

// -------------------- temporal: out += Gt-filter over 12-row groups of vt --------------------
__global__ __launch_bounds__(256) void k_tfilt(float* __restrict__ out) {
    __shared__ float Gts[144];
    int tid = threadIdx.x;
    if (tid < 144) Gts[tid] = g_Gt[tid];
    __syncthreads();
    int b = blockIdx.y;
    int base = blockIdx.x * 256 + tid;
    if (base >= ND) return;
    int g = base >> 6, d = base & 63;
    const float* vb = g_vt + ((size_t)b*3900 + g*12)*64 + d;
    float v[12];
    #pragma unroll
    for (int tp = 0; tp < 12; tp++) v[tp] = vb[tp*64];
    float* ob = out + (size_t)b*TND + base;
    #pragma unroll
    for (int t = 0; t < 12; t++) {
        float a = 0.f;
        #pragma unroll
        for (int tp = 0; tp < 12; tp++) a = fmaf(Gts[t*12 + tp], v[tp], a);
        ob[(size_t)t*ND] += a;
    }
}

// -------------------- spatial attention (fused proj + 2-pass softmax + irfft) --------------------
// static smem: phaseA overlay [0,7216) + persistent [7216,10800)  = 43.2 KB
__global__ __launch_bounds__(256) void k_spatt(const float* __restrict__ Wq, const float* __restrict__ Wk,
                                               const float* __restrict__ Wv, const float* __restrict__ wQ,
                                               const int* __restrict__ sp_modes, float* __restrict__ out) {
    __shared__ float sm[10800];
    float* sxC  = sm;                 // 2048 (phase A)
    float* sxS  = sm + 2048;          // 2048 (phase A)
    float* sW3  = sm + 4096;          // 3120 (phase A)
    float* pers = sm + 7216;
    float* magq = pers;               // 512
    float* magk = pers + 512;         // 512
    float* vRe  = pers + 1024;        // 512
    float* vIm  = pers + 1536;        // 512
    float* dinv = pers + 2048;        // 512
    float* oRe  = pers + 2560;        // 512
    float* oIs  = pers + 3072;        // 512

    int tid = threadIdx.x;
    int bt = blockIdx.x >> 2;
    int h  = blockIdx.x & 3;

    // ---- phase A: load xf (transposed layout) + head weights; magnitudes & vf ----
    for (int i = tid; i < 2048; i += 256) {
        int m = i >> 6, e = i & 63;
        sxC[i] = g_xf[(size_t)m*NCOL + bt*64 + e];
        sxS[i] = g_xf[(size_t)(m + 32)*NCOL + bt*64 + e];
    }
    for (int i = tid; i < 16*64; i += 256) {
        int hd = i >> 6, e = i & 63;
        int row = h*16 + hd;
        sW3[hd*65 + e]          = Wq[row*64 + e];
        sW3[1040 + hd*65 + e]   = Wk[row*64 + e];
        sW3[2080 + hd*65 + e]   = Wv[row*64 + e];
    }
    __syncthreads();
    float invq = g_inv[0], invk = g_inv[1];
    #pragma unroll
    for (int rep = 0; rep < 2; rep++) {
        int p = tid + rep*256;            // (m, hd)
        int m = p >> 4, hd = p & 15;
        float qC=0.f,qS=0.f,kC=0.f,kS=0.f,vC=0.f,vS=0.f;
        #pragma unroll 4
        for (int e = 0; e < 64; e++) {
            float xc = sxC[m*64 + e], xs = sxS[m*64 + e];
            float wq = sW3[hd*65 + e], wk = sW3[1040 + hd*65 + e], wv = sW3[2080 + hd*65 + e];
            qC = fmaf(xc, wq, qC); qS = fmaf(xs, wq, qS);
            kC = fmaf(xc, wk, kC); kS = fmaf(xs, wk, kS);
            vC = fmaf(xc, wv, vC); vS = fmaf(xs, wv, vS);
        }
        magq[p] = sqrtf(qC*qC + qS*qS) * invq;
        magk[p] = sqrtf(kC*kC + kS*kS) * invk;
        vRe[p]  = vC;
        vIm[p]  = -vS;
    }
    __syncthreads();

    // ---- phase B: per-(m1,hd) softmax denominators (no weight table stored) ----
    #pragma unroll
    for (int rep = 0; rep < 2; rep++) {
        int p = tid + rep*256;            // (m1, hd)
        int m1 = p >> 4, hd = p & 15;
        float mq = magq[m1*16 + hd];
        float l0 = SCALE * magk[hd] * mq;
        float e0;
        {
            float t = fmaf(l0, 0.0416666667f, 0.1666666667f);
            t = fmaf(l0, t, 0.5f); t = fmaf(l0, t, 1.0f);
            e0 = (l0 < 0.25f) ? fmaf(l0, t, 1.0f) : __expf(l0);
        }
        float den = e0;
        #pragma unroll 4
        for (int m2 = 1; m2 < 32; m2++) {
            float amp = fabsf(wQ[(m1*31 + m2 - 1)*16 + hd]);
            float l = SCALE * magk[m2*16 + hd] * amp;
            float t = fmaf(l, 0.0416666667f, 0.1666666667f);
            t = fmaf(l, t, 0.5f); t = fmaf(l, t, 1.0f);
            float e = (l < 0.25f) ? fmaf(l, t, 1.0f) : __expf(l);
            den += e;
        }
        dinv[p] = 1.0f / den;
    }
    __syncthreads();

    // ---- phase C: per-(m2,hd) recompute exps, weight by dinv, mean over m1 ----
    #pragma unroll
    for (int rep = 0; rep < 2; rep++) {
        int p = tid + rep*256;            // (m2, hd)
        int m2 = p >> 4, hd = p & 15;
        float mk = SCALE * magk[p];
        float s = 0.f;
        if (m2 == 0) {
            #pragma unroll 4
            for (int m1 = 0; m1 < 32; m1++) {
                float l = mk * magq[m1*16 + hd];
                float t = fmaf(l, 0.0416666667f, 0.1666666667f);
                t = fmaf(l, t, 0.5f); t = fmaf(l, t, 1.0f);
                float e = (l < 0.25f) ? fmaf(l, t, 1.0f) : __expf(l);
                s = fmaf(e, dinv[m1*16 + hd], s);
            }
        } else {
            #pragma unroll 4
            for (int m1 = 0; m1 < 32; m1++) {
                float amp = fabsf(wQ[(m1*31 + m2 - 1)*16 + hd]);
                float l = mk * amp;
                float t = fmaf(l, 0.0416666667f, 0.1666666667f);
                t = fmaf(l, t, 0.5f); t = fmaf(l, t, 1.0f);
                float e = (l < 0.25f) ? fmaf(l, t, 1.0f) : __expf(l);
                s = fmaf(e, dinv[m1*16 + hd], s);
            }
        }
        int f = sp_modes[m2];
        float c = s * (1.0f/32.0f) * ((f == 0) ? 1.0f : 2.0f) * (1.0f/(float)Nn);
        oRe[p] = vRe[p] * c;
        oIs[p] = -vIm[p] * c;
    }
    __syncthreads();

    // ---- phase D: inverse DFT, accumulate into out ----
    for (int n = tid; n < Nn; n += 256) {
        float acc[16];
        #pragma unroll
        for (int hd = 0; hd < 16; hd++) acc[hd] = 0.f;
        #pragma unroll 4
        for (int m = 0; m < 32; m++) {
            float c = g_basisC[m*Nn + n], s = g_basisS[m*Nn + n];
            #pragma unroll
            for (int hd = 0; hd < 16; hd++)
                acc[hd] = fmaf(oRe[m*16 + hd], c, fmaf(oIs[m*16 + hd], s, acc[hd]));
        }
        float4* o4 = (float4*)(out + (size_t)bt*ND + n*64 + h*16);
        #pragma unroll
        for (int q4 = 0; q4 < 4; q4++) {
            float4 v = o4[q4];
            v.x += acc[q4*4 + 0]; v.y += acc[q4*4 + 1];
            v.z += acc[q4*4 + 2]; v.w += acc[q4*4 + 3];
            o4[q4] = v;
        }
    }
}

// -------------------- launch --------------------
extern "C" void kernel_launch(void* const* d_in, const int* in_sizes, int n_in,
                              void* d_out, int out_size) {
    const float* x      = (const float*)d_in[0];
    const float* adj    = (const float*)d_in[1];
    const float* Wq_geo = (const float*)d_in[2];
    const float* Wk_geo = (const float*)d_in[3];
    const float* Wv_geo = (const float*)d_in[4];
    const float* Wv_t   = (const float*)d_in[7];
    const float* W_fc1  = (const float*)d_in[8];
    const float* W_mlp  = (const float*)d_in[9];
    const float* b_mlp  = (const float*)d_in[10];
    const float* wQ     = (const float*)d_in[11];
    const int*   sp_m   = (const int*)d_in[13];
    float* out = (float*)d_out;

    cudaFuncSetAttribute(k_projT, cudaFuncAttributeMaxDynamicSharedMemorySize, PROJT_SMEM);

    k_init  <<<Nn + 1, 128>>>(adj, sp_m);
    k_gram  <<<148, 256>>>(x);
    k_norm  <<<1, 256>>>(Wq_geo, Wk_geo, W_mlp, W_fc1, Wv_t);
    k_dft2  <<<NCOL/128, 256>>>(x);
    k_projT <<<(Bb*Tt*Nn)/128, 256, PROJT_SMEM>>>(x);
    {
        dim3 g(NCOL/128, 3);
        k_gcn2 <<<g, 256>>>(b_mlp, out);                 // writes every output element
    }
    {
        dim3 g((ND + 255)/256, Bb);
        k_tfilt<<<g, 256>>>(out);                        // accumulates
    }
    k_spatt <<<BT*Hh, 256>>>(Wq_geo, Wk_geo, Wv_geo, wQ, sp_m, out);
}

// round 8
// speedup vs baseline: 1.5025x; 1.2404x over previous
#include <cuda_runtime.h>
#include <math.h>
#include <stdint.h>

// Problem constants
#define Bb   32
#define Tt   12
#define Nn   325
#define Dd   64
#define Hh   4
#define HDd  16
#define Mm   32            // M_SP
#define BT   (Bb*Tt)       // 384
#define ND   (Nn*Dd)       // 20800
#define TND  (Tt*Nn*Dd)    // 249600
#define NCOL (BT*64)       // 24576 columns (bt*64+e / bt*64+d)
#define SCALE 0.25f

// -------------------- scratch (device globals; no allocation) --------------------
__device__ float g_xf[BT*64*64];      // DFT, TRANSPOSED: [m][bt*64+e], m<32 cos, m>=32 sin (6 MB)
__device__ float g_xcT[Nn*NCOL];      // (x @ Wc^T) transposed: [n][bt*64+d]  (32 MB)
__device__ float g_vt[BT*Nn*64];      // x @ Wvt^T, row layout (32 MB)
__device__ float g_anormT[Nn*Nn];     // transpose of row-normalized adjacency
__device__ float g_basisC[Mm*Nn];     // [m][n] cos
__device__ float g_basisS[Mm*Nn];     // [m][n] sin
__device__ float g_basisT[Nn*64];     // [n][m] : m<32 cos, m>=32 sin
__device__ float g_Gt[12*12];         // temporal filter (includes 1/6 * 1/12)
__device__ float g_G[64*64];          // Gram X^T X
__device__ float g_WT[64*128];        // [e][c]: c<64 -> Wc[c][e], c>=64 -> Wvt[c-64][e]
__device__ float g_inv[2];            // 1/||q||, 1/||k||

// -------------------- init: anormT, DFT bases, Gt, zero G --------------------
__global__ void k_init(const float* __restrict__ adj, const int* __restrict__ sp_modes) {
    int bx = blockIdx.x, tid = threadIdx.x;
    if (bx < Nn) {
        __shared__ float red[128];
        float s = 0.f;
        for (int k = tid; k < Nn; k += 128) s += adj[bx*Nn + k];
        red[tid] = s; __syncthreads();
        for (int o = 64; o > 0; o >>= 1) { if (tid < o) red[tid] += red[tid+o]; __syncthreads(); }
        float inv = 1.0f / red[0];
        for (int k = tid; k < Nn; k += 128) {
            g_anormT[k*Nn + bx] = adj[bx*Nn + k] * inv;
        }
    } else {
        for (int i = tid; i < Mm*Nn; i += 128) {
            int m = i / Nn, n = i % Nn;
            int f = sp_modes[m];
            int km = (int)(((long long)f * n) % Nn);
            float a = 2.0f * (float)km / (float)Nn;
            g_basisC[i] = cospif(a);
            g_basisS[i] = sinpif(a);
        }
        for (int i = tid; i < Nn*64; i += 128) {
            int n = i >> 6, m = i & 63;
            int f = sp_modes[m & 31];
            int km = (int)(((long long)f * n) % Nn);
            float a = 2.0f * (float)km / (float)Nn;
            g_basisT[i] = (m < 32) ? cospif(a) : sinpif(a);
        }
        for (int i = tid; i < 144; i += 128) {
            int t = i / 12, t2 = i % 12;
            float acc = 1.0f;
            for (int f = 1; f <= 5; f++) acc += 2.0f * cospif((float)(f*(t - t2)) / 6.0f);
            g_Gt[i] = acc * (1.0f/72.0f);
        }
        for (int i = tid; i < 4096; i += 128) g_G[i] = 0.f;
    }
}

// -------------------- Gram: G = X^T X --------------------
__global__ __launch_bounds__(256) void k_gram(const float* __restrict__ x) {
    __shared__ float xs[16][68];
    int tid = threadIdx.x; int ty = tid >> 4, tx = tid & 15;
    float acc[4][4] = {};
    const int nrows = Bb*Tt*Nn;
    const int nch = (nrows + 15) / 16;
    for (int c = blockIdx.x; c < nch; c += gridDim.x) {
        int r0 = c * 16;
        for (int i = tid; i < 16*64; i += 256) {
            int r = i >> 6, e = i & 63;
            xs[r][e] = (r0 + r < nrows) ? x[(size_t)(r0 + r)*64 + e] : 0.f;
        }
        __syncthreads();
        #pragma unroll
        for (int r = 0; r < 16; r++) {
            float a[4], b[4];
            #pragma unroll
            for (int i = 0; i < 4; i++) a[i] = xs[r][ty*4 + i];
            #pragma unroll
            for (int j = 0; j < 4; j++) b[j] = xs[r][tx*4 + j];
            #pragma unroll
            for (int i = 0; i < 4; i++)
                #pragma unroll
                for (int j = 0; j < 4; j++) acc[i][j] = fmaf(a[i], b[j], acc[i][j]);
        }
        __syncthreads();
    }
    #pragma unroll
    for (int i = 0; i < 4; i++)
        #pragma unroll
        for (int j = 0; j < 4; j++)
            atomicAdd(&g_G[(ty*4 + i)*64 + tx*4 + j], acc[i][j]);
}

// -------------------- norms via Gram + combined projection weight g_WT --------------------
__global__ __launch_bounds__(256) void k_norm(const float* __restrict__ Wq, const float* __restrict__ Wk,
                                              const float* __restrict__ Wmlp, const float* __restrict__ Wfc1,
                                              const float* __restrict__ Wvt) {
    __shared__ float Gs[4096];
    __shared__ float red[256];
    int tid = threadIdx.x;
    for (int i = tid; i < 4096; i += 256) Gs[i] = g_G[i];
    __syncthreads();
    float sq = 0.f, sk = 0.f;
    for (int p = tid; p < 4096; p += 256) {
        int d = p >> 6, f = p & 63;
        float aq = 0.f, ak = 0.f;
        #pragma unroll 8
        for (int e = 0; e < 64; e++) {
            float g = Gs[e*64 + f];
            aq = fmaf(Wq[d*64 + e], g, aq);
            ak = fmaf(Wk[d*64 + e], g, ak);
        }
        sq = fmaf(aq, Wq[d*64 + f], sq);
        sk = fmaf(ak, Wk[d*64 + f], sk);
    }
    red[tid] = sq; __syncthreads();
    for (int o = 128; o > 0; o >>= 1) { if (tid < o) red[tid] += red[tid+o]; __syncthreads(); }
    if (tid == 0) g_inv[0] = 1.0f / sqrtf(red[0]);
    __syncthreads();
    red[tid] = sk; __syncthreads();
    for (int o = 128; o > 0; o >>= 1) { if (tid < o) red[tid] += red[tid+o]; __syncthreads(); }
    if (tid == 0) g_inv[1] = 1.0f / sqrtf(red[0]);
    // Wc[e2][d] = sum_e Wmlp[e2,e]*Wfc1[e,d]; store transposed into g_WT[d*128 + e2]
    for (int p = tid; p < 4096; p += 256) {
        int e2 = p >> 6, d = p & 63;
        float a = 0.f;
        #pragma unroll 8
        for (int e = 0; e < 64; e++) a = fmaf(Wmlp[e2*64 + e], Wfc1[e*64 + d], a);
        g_WT[d*128 + e2] = a;
    }
    for (int p = tid; p < 4096; p += 256) {
        int c = p >> 6, e = p & 63;
        g_WT[e*128 + 64 + c] = Wvt[c*64 + e];
    }
}

// -------------------- DFT: per-bt 64x64 tile, double-buffered pipeline --------------------
__global__ __launch_bounds__(256) void k_dft3(const float* __restrict__ x) {
    __shared__ float As[2][25*68];
    __shared__ float Bs[2][25*68];
    int tid = threadIdx.x, ty = tid >> 4, tx = tid & 15;
    int bt = blockIdx.x;                       // 384 blocks, 64 cols each = one bt
    const float* xb = x + (size_t)bt * ND;
    float4 pa[2], pb[2];
    #pragma unroll
    for (int j = 0; j < 2; j++) {
        int idx = tid + j*256;
        if (idx < 400) {
            int kk = idx >> 4, m4 = idx & 15;
            pa[j] = *(const float4*)&g_basisT[kk*64 + m4*4];
            pb[j] = *(const float4*)&xb[kk*64 + m4*4];
        }
    }
    float acc[4][4] = {};
    int p = 0;
    for (int c = 0; c < 13; c++) {
        #pragma unroll
        for (int j = 0; j < 2; j++) {
            int idx = tid + j*256;
            if (idx < 400) {
                int kk = idx >> 4, m4 = idx & 15;
                *(float4*)&As[p][kk*68 + m4*4] = pa[j];
                *(float4*)&Bs[p][kk*68 + m4*4] = pb[j];
            }
        }
        __syncthreads();
        if (c < 12) {
            int k0 = (c + 1) * 25;
            #pragma unroll
            for (int j = 0; j < 2; j++) {
                int idx = tid + j*256;
                if (idx < 400) {
                    int kk = idx >> 4, m4 = idx & 15;
                    pa[j] = *(const float4*)&g_basisT[(k0 + kk)*64 + m4*4];
                    pb[j] = *(const float4*)&xb[(k0 + kk)*64 + m4*4];
                }
            }
        }
        #pragma unroll
        for (int kk = 0; kk < 25; kk++) {
            float a[4], b[4];
            *(float4*)a = *(const float4*)&As[p][kk*68 + ty*4];
            *(float4*)b = *(const float4*)&Bs[p][kk*68 + tx*4];
            #pragma unroll
            for (int i = 0; i < 4; i++)
                #pragma unroll
                for (int j = 0; j < 4; j++) acc[i][j] = fmaf(a[i], b[j], acc[i][j]);
        }
        p ^= 1;
    }
    #pragma unroll
    for (int i = 0; i < 4; i++) {
        float4 v = make_float4(acc[i][0], acc[i][1], acc[i][2], acc[i][3]);
        *(float4*)&g_xf[(size_t)(ty*4 + i)*NCOL + bt*64 + tx*4] = v;
    }
}

// -------------------- fused projection: [xcT | vt] = X @ [Wc ; Wvt]^T, 128x128 tiles --------------------
#define PROJT_SMEM ((64*133 + 64*132) * 4)
__global__ __launch_bounds__(256) void k_projT(const float* __restrict__ x) {
    extern __shared__ float sm[];
    float* XsT = sm;            // [e][r], stride 133
    float* Ws  = sm + 64*133;   // [e][c], stride 132
    int tid = threadIdx.x, ty = tid >> 4, tx = tid & 15;
    int r0 = blockIdx.x * 128;  // 975 blocks, exact
    const float4* x4 = (const float4*)(x + (size_t)r0*64);
    for (int i = tid; i < 128*16; i += 256) {
        int r = i >> 4, e4 = i & 15;
        float4 v = x4[r*16 + e4];
        XsT[(e4*4 + 0)*133 + r] = v.x;
        XsT[(e4*4 + 1)*133 + r] = v.y;
        XsT[(e4*4 + 2)*133 + r] = v.z;
        XsT[(e4*4 + 3)*133 + r] = v.w;
    }
    for (int i = tid; i < 64*128; i += 256) {
        int e = i >> 7, c = i & 127;
        Ws[e*132 + c] = g_WT[i];
    }
    __syncthreads();
    float acc[8][8] = {};
    #pragma unroll 4
    for (int e = 0; e < 64; e++) {
        float a[8], b[8];
        #pragma unroll
        for (int i = 0; i < 8; i++) a[i] = XsT[e*133 + ty*8 + i];
        #pragma unroll
        for (int j = 0; j < 8; j++) b[j] = Ws[e*132 + tx*8 + j];
        #pragma unroll
        for (int i = 0; i < 8; i++)
            #pragma unroll
            for (int j = 0; j < 8; j++) acc[i][j] = fmaf(a[i], b[j], acc[i][j]);
    }
    #pragma unroll
    for (int i = 0; i < 8; i++) {
        int r = r0 + ty*8 + i;
        int bt = r / Nn, n = r - bt*Nn;
        if (tx < 8) {
            float* o = g_xcT + (size_t)n*NCOL + bt*64 + tx*8;
            #pragma unroll
            for (int j = 0; j < 8; j++) o[j] = acc[i][j];
        } else {
            float* o = g_vt + (size_t)r*64 + (tx*8 - 64);
            #pragma unroll
            for (int j = 0; j < 8; j++) o[j] = acc[i][j];
        }
    }
}

// -------------------- GCN GEMM: out = anorm(325x325) @ xcT(325x24576) + bias, pipelined --------------------
__global__ __launch_bounds__(256, 2) void k_gcn3(const float* __restrict__ bmlp, float* __restrict__ out) {
    __shared__ float As[2][16*132];
    __shared__ float Bs[2][16*132];
    __shared__ float bsm[128];
    int tid = threadIdx.x, ty = tid >> 4, tx = tid & 15;
    int c0 = blockIdx.x * 128;
    int n0 = blockIdx.y * 128;
    if (tid < 128) bsm[tid] = bmlp[(c0 + tid) & 63];
    float ra[8];
    float4 rb[2];
    const float4 z4 = make_float4(0.f, 0.f, 0.f, 0.f);
    // prefetch chunk 0
    #pragma unroll
    for (int j = 0; j < 8; j++) {
        int i = tid + j*256;
        int kk = i >> 7, col = i & 127;
        ra[j] = (kk < Nn && n0 + col < Nn) ? g_anormT[kk*Nn + n0 + col] : 0.f;
    }
    #pragma unroll
    for (int j = 0; j < 2; j++) {
        int i = tid + j*256;
        int kk = i >> 5, c4 = i & 31;
        rb[j] = (kk < Nn) ? *(const float4*)&g_xcT[(size_t)kk*NCOL + c0 + c4*4] : z4;
    }
    float acc[8][8] = {};
    int p = 0;
    for (int c = 0; c < 21; c++) {
        #pragma unroll
        for (int j = 0; j < 8; j++) {
            int i = tid + j*256;
            As[p][(i >> 7)*132 + (i & 127)] = ra[j];
        }
        #pragma unroll
        for (int j = 0; j < 2; j++) {
            int i = tid + j*256;
            *(float4*)&Bs[p][(i >> 5)*132 + (i & 31)*4] = rb[j];
        }
        __syncthreads();
        if (c < 20) {
            int k0 = (c + 1) * 16;
            #pragma unroll
            for (int j = 0; j < 8; j++) {
                int i = tid + j*256;
                int kk = k0 + (i >> 7), col = i & 127;
                ra[j] = (kk < Nn && n0 + col < Nn) ? g_anormT[kk*Nn + n0 + col] : 0.f;
            }
            #pragma unroll
            for (int j = 0; j < 2; j++) {
                int i = tid + j*256;
                int kk = k0 + (i >> 5), c4 = i & 31;
                rb[j] = (kk < Nn) ? *(const float4*)&g_xcT[(size_t)kk*NCOL + c0 + c4*4] : z4;
            }
        }
        #pragma unroll
        for (int kk = 0; kk < 16; kk++) {
            float a[8], b[8];
            *(float4*)&a[0] = *(const float4*)&As[p][kk*132 + ty*8];
            *(float4*)&a[4] = *(const float4*)&As[p][kk*132 + ty*8 + 4];
            *(float4*)&b[0] = *(const float4*)&Bs[p][kk*132 + tx*8];
            *(float4*)&b[4] = *(const float4*)&Bs[p][kk*132 + tx*8 + 4];
            #pragma unroll
            for (int i = 0; i < 8; i++)
                #pragma unroll
                for (int j = 0; j < 8; j++) acc[i][j] = fmaf(a[i], b[j], acc[i][j]);
        }
        p ^= 1;
    }
    int cloc = tx*8;
    int bt = (c0 + cloc) >> 6;
    int d  = (c0 + cloc) & 63;
    #pragma unroll
    for (int i = 0; i < 8; i++) {
        int n = n0 + ty*8 + i;
        if (n < Nn) {
            float* o = out + (size_t)bt*ND + n*64 + d;
            #pragma unroll
            for (int j = 0; j < 8; j++) o[j] = acc[i][j] + bsm[cloc + j];
        }
    }
}

// -------------------- temporal: out += Gt-filter over 12-row groups of vt --------------------
__global__ __launch_bounds__(256) void k_tfilt(float* __restrict__ out) {
    __shared__ float Gts[144];
    int tid = threadIdx.x;
    if (tid < 144) Gts[tid] = g_Gt[tid];
    __syncthreads();
    int b = blockIdx.y;
    int base = blockIdx.x * 256 + tid;
    if (base >= ND) return;
    int g = base >> 6, d = base & 63;
    const float* vb = g_vt + ((size_t)b*3900 + g*12)*64 + d;
    float v[12];
    #pragma unroll
    for (int tp = 0; tp < 12; tp++) v[tp] = vb[tp*64];
    float* ob = out + (size_t)b*TND + base;
    #pragma unroll
    for (int t = 0; t < 12; t++) {
        float a = 0.f;
        #pragma unroll
        for (int tp = 0; tp < 12; tp++) a = fmaf(Gts[t*12 + tp], v[tp], a);
        ob[(size_t)t*ND] += a;
    }
}

// -------------------- spatial attention (fused proj + 2-pass softmax + irfft) --------------------
__global__ __launch_bounds__(256) void k_spatt(const float* __restrict__ Wq, const float* __restrict__ Wk,
                                               const float* __restrict__ Wv, const float* __restrict__ wQ,
                                               const int* __restrict__ sp_modes, float* __restrict__ out) {
    __shared__ float sm[10800];
    float* sxC  = sm;
    float* sxS  = sm + 2048;
    float* sW3  = sm + 4096;
    float* pers = sm + 7216;
    float* magq = pers;
    float* magk = pers + 512;
    float* vRe  = pers + 1024;
    float* vIm  = pers + 1536;
    float* dinv = pers + 2048;
    float* oRe  = pers + 2560;
    float* oIs  = pers + 3072;

    int tid = threadIdx.x;
    int bt = blockIdx.x >> 2;
    int h  = blockIdx.x & 3;

    for (int i = tid; i < 2048; i += 256) {
        int m = i >> 6, e = i & 63;
        sxC[i] = g_xf[(size_t)m*NCOL + bt*64 + e];
        sxS[i] = g_xf[(size_t)(m + 32)*NCOL + bt*64 + e];
    }
    for (int i = tid; i < 16*64; i += 256) {
        int hd = i >> 6, e = i & 63;
        int row = h*16 + hd;
        sW3[hd*65 + e]          = Wq[row*64 + e];
        sW3[1040 + hd*65 + e]   = Wk[row*64 + e];
        sW3[2080 + hd*65 + e]   = Wv[row*64 + e];
    }
    __syncthreads();
    float invq = g_inv[0], invk = g_inv[1];
    #pragma unroll
    for (int rep = 0; rep < 2; rep++) {
        int p = tid + rep*256;
        int m = p >> 4, hd = p & 15;
        float qC=0.f,qS=0.f,kC=0.f,kS=0.f,vC=0.f,vS=0.f;
        #pragma unroll 4
        for (int e = 0; e < 64; e++) {
            float xc = sxC[m*64 + e], xs = sxS[m*64 + e];
            float wq = sW3[hd*65 + e], wk = sW3[1040 + hd*65 + e], wv = sW3[2080 + hd*65 + e];
            qC = fmaf(xc, wq, qC); qS = fmaf(xs, wq, qS);
            kC = fmaf(xc, wk, kC); kS = fmaf(xs, wk, kS);
            vC = fmaf(xc, wv, vC); vS = fmaf(xs, wv, vS);
        }
        magq[p] = sqrtf(qC*qC + qS*qS) * invq;
        magk[p] = sqrtf(kC*kC + kS*kS) * invk;
        vRe[p]  = vC;
        vIm[p]  = -vS;
    }
    __syncthreads();

    #pragma unroll
    for (int rep = 0; rep < 2; rep++) {
        int p = tid + rep*256;
        int m1 = p >> 4, hd = p & 15;
        float mq = magq[m1*16 + hd];
        float l0 = SCALE * magk[hd] * mq;
        float e0;
        {
            float t = fmaf(l0, 0.0416666667f, 0.1666666667f);
            t = fmaf(l0, t, 0.5f); t = fmaf(l0, t, 1.0f);
            e0 = (l0 < 0.25f) ? fmaf(l0, t, 1.0f) : __expf(l0);
        }
        float den = e0;
        #pragma unroll 4
        for (int m2 = 1; m2 < 32; m2++) {
            float amp = fabsf(wQ[(m1*31 + m2 - 1)*16 + hd]);
            float l = SCALE * magk[m2*16 + hd] * amp;
            float t = fmaf(l, 0.0416666667f, 0.1666666667f);
            t = fmaf(l, t, 0.5f); t = fmaf(l, t, 1.0f);
            float e = (l < 0.25f) ? fmaf(l, t, 1.0f) : __expf(l);
            den += e;
        }
        dinv[p] = 1.0f / den;
    }
    __syncthreads();

    #pragma unroll
    for (int rep = 0; rep < 2; rep++) {
        int p = tid + rep*256;
        int m2 = p >> 4, hd = p & 15;
        float mk = SCALE * magk[p];
        float s = 0.f;
        if (m2 == 0) {
            #pragma unroll 4
            for (int m1 = 0; m1 < 32; m1++) {
                float l = mk * magq[m1*16 + hd];
                float t = fmaf(l, 0.0416666667f, 0.1666666667f);
                t = fmaf(l, t, 0.5f); t = fmaf(l, t, 1.0f);
                float e = (l < 0.25f) ? fmaf(l, t, 1.0f) : __expf(l);
                s = fmaf(e, dinv[m1*16 + hd], s);
            }
        } else {
            #pragma unroll 4
            for (int m1 = 0; m1 < 32; m1++) {
                float amp = fabsf(wQ[(m1*31 + m2 - 1)*16 + hd]);
                float l = mk * amp;
                float t = fmaf(l, 0.0416666667f, 0.1666666667f);
                t = fmaf(l, t, 0.5f); t = fmaf(l, t, 1.0f);
                float e = (l < 0.25f) ? fmaf(l, t, 1.0f) : __expf(l);
                s = fmaf(e, dinv[m1*16 + hd], s);
            }
        }
        int f = sp_modes[m2];
        float c = s * (1.0f/32.0f) * ((f == 0) ? 1.0f : 2.0f) * (1.0f/(float)Nn);
        oRe[p] = vRe[p] * c;
        oIs[p] = -vIm[p] * c;
    }
    __syncthreads();

    for (int n = tid; n < Nn; n += 256) {
        float acc[16];
        #pragma unroll
        for (int hd = 0; hd < 16; hd++) acc[hd] = 0.f;
        #pragma unroll 4
        for (int m = 0; m < 32; m++) {
            float c = g_basisC[m*Nn + n], s = g_basisS[m*Nn + n];
            #pragma unroll
            for (int hd = 0; hd < 16; hd++)
                acc[hd] = fmaf(oRe[m*16 + hd], c, fmaf(oIs[m*16 + hd], s, acc[hd]));
        }
        float4* o4 = (float4*)(out + (size_t)bt*ND + n*64 + h*16);
        #pragma unroll
        for (int q4 = 0; q4 < 4; q4++) {
            float4 v = o4[q4];
            v.x += acc[q4*4 + 0]; v.y += acc[q4*4 + 1];
            v.z += acc[q4*4 + 2]; v.w += acc[q4*4 + 3];
            o4[q4] = v;
        }
    }
}

// -------------------- launch --------------------
extern "C" void kernel_launch(void* const* d_in, const int* in_sizes, int n_in,
                              void* d_out, int out_size) {
    const float* x      = (const float*)d_in[0];
    const float* adj    = (const float*)d_in[1];
    const float* Wq_geo = (const float*)d_in[2];
    const float* Wk_geo = (const float*)d_in[3];
    const float* Wv_geo = (const float*)d_in[4];
    const float* Wv_t   = (const float*)d_in[7];
    const float* W_fc1  = (const float*)d_in[8];
    const float* W_mlp  = (const float*)d_in[9];
    const float* b_mlp  = (const float*)d_in[10];
    const float* wQ     = (const float*)d_in[11];
    const int*   sp_m   = (const int*)d_in[13];
    float* out = (float*)d_out;

    cudaFuncSetAttribute(k_projT, cudaFuncAttributeMaxDynamicSharedMemorySize, PROJT_SMEM);

    k_init  <<<Nn + 1, 128>>>(adj, sp_m);
    k_gram  <<<444, 256>>>(x);
    k_norm  <<<1, 256>>>(Wq_geo, Wk_geo, W_mlp, W_fc1, Wv_t);
    k_dft3  <<<BT, 256>>>(x);
    k_projT <<<(Bb*Tt*Nn)/128, 256, PROJT_SMEM>>>(x);
    {
        dim3 g(NCOL/128, 3);
        k_gcn3 <<<g, 256>>>(b_mlp, out);                 // writes every output element
    }
    {
        dim3 g((ND + 255)/256, Bb);
        k_tfilt<<<g, 256>>>(out);                        // accumulates
    }
    k_spatt <<<BT*Hh, 256>>>(Wq_geo, Wk_geo, Wv_geo, wQ, sp_m, out);
}